// round 8
// baseline (speedup 1.0000x reference)
#include <cuda_runtime.h>
#include <cuda_bf16.h>

namespace {

constexpr int NQ     = 12;
constexpr int DIM    = 4096;
constexpr int LAYERS = 8;
constexpr int FEAT   = 3072;
constexpr int NCLASS = 10;
constexpr int TPB    = 256;   // threads per CTA; CTA simulates TWO states
constexpr int AMPS   = 16;    // amplitudes per thread per state
constexpr int RS     = 17;    // smem row stride in float2 units

// Amplitude index i (12 bits). Three register-local arrangements:
//   A: i = (t<<4) | r          bits 0-3  local   (thread t, reg r)
//   C: i = (u<<8)|(rc<<4)|w    bits 4-7  local   (u = t>>4, w = t&15)
//   B: i = (rp<<8) | t         bits 8-11 local
// buf holds the state as a 256x16 matrix: buf[(i>>4)*RS + (i&15)].
// Qubit q acts on bit p = 11 - q; the per-layer CNOT chain is the Gray map
// j = i ^ (i>>1). Tan-form butterflies; cos product folded into the norm.
// No shuffles anywhere in the main loop.

__global__ void __launch_bounds__(TPB, 4) qnn_kernel(
    const float* __restrict__ x,       // [B, 3072]
    const float* __restrict__ angles,  // [8, 12]
    const float* __restrict__ W,       // [10, 4096]
    const float* __restrict__ bias,    // [10]
    float* __restrict__ out)           // [B, 10]
{
    __shared__ float  s_t[LAYERS][NQ];   // tan table [layer][bit pos]
    __shared__ float2 buf[TPB * RS];     // exchange buffer (34816 B)
    __shared__ float  s_prod[8];         // per-warp cos products
    __shared__ float2 s_norm[8];         // per-warp sum-of-squares
    __shared__ float2 sred[8 * NCLASS];  // epilogue partials

    const int t    = threadIdx.x;
    const int lane = t & 31;
    const int warp = t >> 5;
    const int bb   = blockIdx.x;

    // ---- trig: tan per gate; accumulate global cos product ----
    float cp = 1.0f;
    if (t < LAYERS * NQ) {
        const int l = t / NQ;
        const int q = t - l * NQ;
        const float a = angles[t];
        const int p = NQ - 1 - q;        // qubit q -> bit position p
        const float c = cosf(a);
        s_t[l][p] = sinf(a) / c;
        cp = c;
    }
    #pragma unroll
    for (int o = 16; o > 0; o >>= 1)
        cp *= __shfl_xor_sync(0xffffffffu, cp, o);
    if (lane == 0) s_prod[warp] = cp;

    // ---- load two input rows (pad 3072 -> 4096), arrangement A ----
    float v0[AMPS], v1[AMPS];
    if (t < FEAT / AMPS) {   // t < 192
        const float4* x0 = reinterpret_cast<const float4*>(x)
                         + (size_t)(2 * bb)     * (FEAT / 4) + t * (AMPS / 4);
        const float4* x1 = reinterpret_cast<const float4*>(x)
                         + (size_t)(2 * bb + 1) * (FEAT / 4) + t * (AMPS / 4);
        #pragma unroll
        for (int i = 0; i < AMPS / 4; i++) {
            const float4 a4 = x0[i];
            v0[4*i+0] = a4.x; v0[4*i+1] = a4.y; v0[4*i+2] = a4.z; v0[4*i+3] = a4.w;
            const float4 b4 = x1[i];
            v1[4*i+0] = b4.x; v1[4*i+1] = b4.y; v1[4*i+2] = b4.z; v1[4*i+3] = b4.w;
        }
    } else {
        #pragma unroll
        for (int r = 0; r < AMPS; r++) { v0[r] = 0.0f; v1[r] = 0.0f; }
    }

    // ---- per-state L2 norm, fold in cos product ----
    float q0 = 0.0f, q1 = 0.0f;
    #pragma unroll
    for (int r = 0; r < AMPS; r++) {
        q0 = fmaf(v0[r], v0[r], q0);
        q1 = fmaf(v1[r], v1[r], q1);
    }
    #pragma unroll
    for (int o = 16; o > 0; o >>= 1) {
        q0 += __shfl_xor_sync(0xffffffffu, q0, o);
        q1 += __shfl_xor_sync(0xffffffffu, q1, o);
    }
    if (lane == 0) s_norm[warp] = make_float2(q0, q1);
    __syncthreads();
    {
        float t0 = 0.0f, t1 = 0.0f, ctot = 1.0f;
        #pragma unroll
        for (int w = 0; w < 8; w++) {
            t0 += s_norm[w].x; t1 += s_norm[w].y; ctot *= s_prod[w];
        }
        const float rn0 = rsqrtf(t0) * ctot;
        const float rn1 = rsqrtf(t1) * ctot;
        #pragma unroll
        for (int r = 0; r < AMPS; r++) { v0[r] *= rn0; v1[r] *= rn1; }
    }

    const int g_t   = t ^ (t >> 1);              // 8-bit Gray of thread id
    const int u     = t >> 4;
    const int w     = t & 15;
    const int baseA = t * RS;                    // + r
    const int baseC = (u << 4) * RS + w;         // + rc*RS
    const int baseB = (u) * RS + w;              // + (rp<<4)*RS

    #pragma unroll 1
    for (int l = 0; l < LAYERS; l++) {
        // ---- gates on bits 0..3 (register butterflies, arrangement A) ----
        #pragma unroll
        for (int p = 0; p < 4; p++) {
            const float tg = s_t[l][p];
            const int m = 1 << p;
            #pragma unroll
            for (int lo = 0; lo < AMPS; lo += 2 * m)
                #pragma unroll
                for (int k = 0; k < m; k++) {
                    const int r0 = lo + k, r1 = r0 + m;
                    float a0 = v0[r0], a1 = v0[r1];
                    v0[r0] = fmaf(-tg, a1, a0);
                    v0[r1] = fmaf( tg, a0, a1);
                    a0 = v1[r0]; a1 = v1[r1];
                    v1[r0] = fmaf(-tg, a1, a0);
                    v1[r1] = fmaf( tg, a0, a1);
                }
        }

        // ---- W1: write A (own row) ----
        #pragma unroll
        for (int r = 0; r < AMPS; r++)
            buf[baseA + r] = make_float2(v0[r], v1[r]);
        __syncthreads();

        // ---- R1: read C ----
        #pragma unroll
        for (int rc = 0; rc < AMPS; rc++) {
            const float2 w2 = buf[baseC + rc * RS];
            v0[rc] = w2.x; v1[rc] = w2.y;
        }

        // ---- gates on bits 4..7 (register butterflies, arrangement C) ----
        #pragma unroll
        for (int p = 0; p < 4; p++) {
            const float tg = s_t[l][p + 4];
            const int m = 1 << p;
            #pragma unroll
            for (int lo = 0; lo < AMPS; lo += 2 * m)
                #pragma unroll
                for (int k = 0; k < m; k++) {
                    const int r0 = lo + k, r1 = r0 + m;
                    float a0 = v0[r0], a1 = v0[r1];
                    v0[r0] = fmaf(-tg, a1, a0);
                    v0[r1] = fmaf( tg, a0, a1);
                    a0 = v1[r0]; a1 = v1[r1];
                    v1[r0] = fmaf(-tg, a1, a0);
                    v1[r1] = fmaf( tg, a0, a1);
                }
        }

        // ---- W2: write C (same addresses this thread just read -> no bar) ----
        #pragma unroll
        for (int rc = 0; rc < AMPS; rc++)
            buf[baseC + rc * RS] = make_float2(v0[rc], v1[rc]);
        __syncthreads();

        // ---- R2: read B ----
        #pragma unroll
        for (int rp = 0; rp < AMPS; rp++) {
            const float2 w2 = buf[baseB + (rp << 4) * RS];
            v0[rp] = w2.x; v1[rp] = w2.y;
        }

        // ---- gates on bits 8..11 (register butterflies, arrangement B) ----
        #pragma unroll
        for (int p = 0; p < 4; p++) {
            const float tg = s_t[l][p + 8];
            const int m = 1 << p;
            #pragma unroll
            for (int lo = 0; lo < AMPS; lo += 2 * m)
                #pragma unroll
                for (int k = 0; k < m; k++) {
                    const int r0 = lo + k, r1 = r0 + m;
                    float a0 = v0[r0], a1 = v0[r1];
                    v0[r0] = fmaf(-tg, a1, a0);
                    v0[r1] = fmaf( tg, a0, a1);
                    a0 = v1[r0]; a1 = v1[r1];
                    v1[r0] = fmaf(-tg, a1, a0);
                    v1[r1] = fmaf( tg, a0, a1);
                }
        }

        __syncthreads();   // WAR: all B-reads done before gray scatter writes

        // ---- W3: Gray scatter, j = i ^ (i>>1), i = (rp<<8)|t ----
        #pragma unroll
        for (int rp = 0; rp < AMPS; rp++) {
            const int j = ((rp << 8) ^ (rp << 7)) ^ g_t;
            buf[(j >> 4) * RS + (j & 15)] = make_float2(v0[rp], v1[rp]);
        }
        __syncthreads();

        // ---- R3: read A (own row; next W1 is same row -> no extra bar) ----
        #pragma unroll
        for (int r = 0; r < AMPS; r++) {
            const float2 w2 = buf[baseA + r];
            v0[r] = w2.x; v1[r] = w2.y;
        }
    }

    // ---- probabilities ----
    #pragma unroll
    for (int r = 0; r < AMPS; r++) { v0[r] *= v0[r]; v1[r] *= v1[r]; }

    // ---- readout: out[k] = sum_i probs[i] * W[k,i] + b[k], both states ----
    #pragma unroll 1
    for (int k = 0; k < NCLASS; k++) {
        const float4* w4 = reinterpret_cast<const float4*>(W + (size_t)k * DIM)
                         + t * (AMPS / 4);
        float a0 = 0.0f, a1 = 0.0f;
        #pragma unroll
        for (int i = 0; i < AMPS / 4; i++) {
            const float4 ww = w4[i];
            a0 = fmaf(v0[4*i+0], ww.x, a0);  a1 = fmaf(v1[4*i+0], ww.x, a1);
            a0 = fmaf(v0[4*i+1], ww.y, a0);  a1 = fmaf(v1[4*i+1], ww.y, a1);
            a0 = fmaf(v0[4*i+2], ww.z, a0);  a1 = fmaf(v1[4*i+2], ww.z, a1);
            a0 = fmaf(v0[4*i+3], ww.w, a0);  a1 = fmaf(v1[4*i+3], ww.w, a1);
        }
        #pragma unroll
        for (int o = 16; o > 0; o >>= 1) {
            a0 += __shfl_xor_sync(0xffffffffu, a0, o);
            a1 += __shfl_xor_sync(0xffffffffu, a1, o);
        }
        if (lane == 0) sred[k * 8 + warp] = make_float2(a0, a1);
    }
    __syncthreads();
    if (t < NCLASS) {
        float a0 = bias[t], a1 = a0;
        #pragma unroll
        for (int wi = 0; wi < 8; wi++) {
            a0 += sred[t * 8 + wi].x;
            a1 += sred[t * 8 + wi].y;
        }
        out[(size_t)(2 * bb)     * NCLASS + t] = a0;
        out[(size_t)(2 * bb + 1) * NCLASS + t] = a1;
    }
}

} // namespace

extern "C" void kernel_launch(void* const* d_in, const int* in_sizes, int n_in,
                              void* d_out, int out_size) {
    const float* x      = (const float*)d_in[0];
    const float* angles = (const float*)d_in[1];
    const float* W      = (const float*)d_in[2];
    const float* bias   = (const float*)d_in[3];
    const int batch = in_sizes[0] / FEAT;   // 2048
    qnn_kernel<<<batch / 2, TPB>>>(x, angles, W, bias, (float*)d_out);
}

// round 9
// speedup vs baseline: 2.1179x; 2.1179x over previous
#include <cuda_runtime.h>
#include <cuda_bf16.h>

namespace {

constexpr int NQ     = 12;
constexpr int DIM    = 4096;
constexpr int LAYERS = 8;
constexpr int FEAT   = 3072;
constexpr int NCLASS = 10;
constexpr int TPB    = 256;   // threads per CTA; CTA simulates TWO states
constexpr int AMPS   = 16;    // amplitudes per thread per state
constexpr int RS     = 17;    // smem row stride in float2 units

// Arrangement A: amplitude i = (t<<4) | r   (bits 0-3 register-local,
//   bits 4-8 lane, bits 9-11 warp)
// Arrangement B: amplitude i = (rp<<8) | t  (bits 8-11 register-local)
// Qubit q acts on bit p = 11 - q. CNOT chain == Gray map j = i ^ (i>>1).
// Tan-form butterflies; cos product folded into normalization.
// Two batch rows per CTA as float2 through shared exchanges.
// launch_bounds(256,3): 85-reg cap -- gives ptxas slack above the ~70-reg
// natural demand so the 32 state floats + staging never spill (the 64-reg
// cap in the previous variant was pinned and spilling to local).

__global__ void __launch_bounds__(TPB, 3) qnn_kernel(
    const float* __restrict__ x,       // [B, 3072]
    const float* __restrict__ angles,  // [8, 12]
    const float* __restrict__ W,       // [10, 4096]
    const float* __restrict__ bias,    // [10]
    float* __restrict__ out)           // [B, 10]
{
    __shared__ float  s_t[LAYERS][NQ];     // tan table [layer][bit pos]
    __shared__ float2 buf[TPB * RS];       // exchange buffer (34816 B)
    __shared__ float  s_prod[8];           // per-warp cos products
    __shared__ float2 s_norm[8];           // per-warp sum-of-squares (2 states)
    __shared__ float2 sred[8 * NCLASS];    // epilogue partials

    const int t    = threadIdx.x;
    const int lane = t & 31;
    const int warp = t >> 5;
    const int bb   = blockIdx.x;

    // ---- trig: tan per gate; accumulate global cos product ----
    float cp = 1.0f;
    if (t < LAYERS * NQ) {
        const int l = t / NQ;
        const int q = t - l * NQ;
        const float a = angles[t];
        const int p = NQ - 1 - q;           // qubit q -> bit position p
        const float c = cosf(a);
        s_t[l][p] = sinf(a) / c;
        cp = c;
    }
    #pragma unroll
    for (int o = 16; o > 0; o >>= 1)
        cp *= __shfl_xor_sync(0xffffffffu, cp, o);
    if (lane == 0) s_prod[warp] = cp;

    // ---- load two input rows (pad 3072 -> 4096), arrangement A ----
    float v0[AMPS], v1[AMPS];
    if (t < FEAT / AMPS) {   // t < 192
        const float4* x0 = reinterpret_cast<const float4*>(x)
                         + (size_t)(2 * bb)     * (FEAT / 4) + t * (AMPS / 4);
        const float4* x1 = reinterpret_cast<const float4*>(x)
                         + (size_t)(2 * bb + 1) * (FEAT / 4) + t * (AMPS / 4);
        #pragma unroll
        for (int i = 0; i < AMPS / 4; i++) {
            const float4 a4 = x0[i];
            v0[4*i+0] = a4.x; v0[4*i+1] = a4.y; v0[4*i+2] = a4.z; v0[4*i+3] = a4.w;
            const float4 b4 = x1[i];
            v1[4*i+0] = b4.x; v1[4*i+1] = b4.y; v1[4*i+2] = b4.z; v1[4*i+3] = b4.w;
        }
    } else {
        #pragma unroll
        for (int r = 0; r < AMPS; r++) { v0[r] = 0.0f; v1[r] = 0.0f; }
    }

    // ---- per-state L2 norm, fold in cos product ----
    float q0 = 0.0f, q1 = 0.0f;
    #pragma unroll
    for (int r = 0; r < AMPS; r++) {
        q0 = fmaf(v0[r], v0[r], q0);
        q1 = fmaf(v1[r], v1[r], q1);
    }
    #pragma unroll
    for (int o = 16; o > 0; o >>= 1) {
        q0 += __shfl_xor_sync(0xffffffffu, q0, o);
        q1 += __shfl_xor_sync(0xffffffffu, q1, o);
    }
    if (lane == 0) s_norm[warp] = make_float2(q0, q1);
    __syncthreads();   // publishes trig table, s_prod, s_norm
    {
        float t0 = 0.0f, t1 = 0.0f, ctot = 1.0f;
        #pragma unroll
        for (int w = 0; w < 8; w++) {
            t0 += s_norm[w].x; t1 += s_norm[w].y; ctot *= s_prod[w];
        }
        const float rn0 = rsqrtf(t0) * ctot;
        const float rn1 = rsqrtf(t1) * ctot;
        #pragma unroll
        for (int r = 0; r < AMPS; r++) { v0[r] *= rn0; v1[r] *= rn1; }
    }

    const int g_t   = t ^ (t >> 1);                 // 8-bit Gray of thread id
    const int baseA = t * RS;
    const int baseB = (t >> 4) * RS + (t & 15);     // + (rp<<4)*RS per rp

    #pragma unroll 1
    for (int l = 0; l < LAYERS; l++) {
        // ---- gates on bits 0..3 (register butterflies, both states) ----
        #pragma unroll
        for (int p = 0; p < 4; p++) {
            const float tg = s_t[l][p];
            const int m = 1 << p;
            #pragma unroll
            for (int lo = 0; lo < AMPS; lo += 2 * m)
                #pragma unroll
                for (int k = 0; k < m; k++) {
                    const int r0 = lo + k, r1 = r0 + m;
                    float a0 = v0[r0], a1 = v0[r1];
                    v0[r0] = fmaf(-tg, a1, a0);
                    v0[r1] = fmaf( tg, a0, a1);
                    a0 = v1[r0]; a1 = v1[r1];
                    v1[r0] = fmaf(-tg, a1, a0);
                    v1[r1] = fmaf( tg, a0, a1);
                }
        }

        // ---- gates on bits 4..7 via shfl_xor (lane bits 0..3) ----
        #pragma unroll
        for (int p = 4; p < 8; p++) {
            const float tg = s_t[l][p];
            const int mask = 1 << (p - 4);
            const float se = (lane & mask) ? tg : -tg;
            #pragma unroll
            for (int r = 0; r < AMPS; r++) {
                const float p0 = __shfl_xor_sync(0xffffffffu, v0[r], mask);
                const float p1 = __shfl_xor_sync(0xffffffffu, v1[r], mask);
                v0[r] = fmaf(se, p0, v0[r]);
                v1[r] = fmaf(se, p1, v1[r]);
            }
        }

        // ---- transpose A -> B ----
        #pragma unroll
        for (int r = 0; r < AMPS; r++)
            buf[baseA + r] = make_float2(v0[r], v1[r]);
        __syncthreads();
        #pragma unroll
        for (int rp = 0; rp < AMPS; rp++) {
            const float2 w2 = buf[baseB + (rp << 4) * RS];
            v0[rp] = w2.x; v1[rp] = w2.y;
        }

        // ---- gates on bits 8..11 (register butterflies in B) ----
        #pragma unroll
        for (int p = 0; p < 4; p++) {
            const float tg = s_t[l][p + 8];
            const int m = 1 << p;
            #pragma unroll
            for (int lo = 0; lo < AMPS; lo += 2 * m)
                #pragma unroll
                for (int k = 0; k < m; k++) {
                    const int r0 = lo + k, r1 = r0 + m;
                    float a0 = v0[r0], a1 = v0[r1];
                    v0[r0] = fmaf(-tg, a1, a0);
                    v0[r1] = fmaf( tg, a0, a1);
                    a0 = v1[r0]; a1 = v1[r1];
                    v1[r0] = fmaf(-tg, a1, a0);
                    v1[r1] = fmaf( tg, a0, a1);
                }
        }

        __syncthreads();   // WAR: transpose reads complete before scatter

        // ---- Gray scatter B -> A: j = i ^ (i>>1), i = (rp<<8)|t ----
        #pragma unroll
        for (int rp = 0; rp < AMPS; rp++) {
            const int j = ((rp << 8) ^ (rp << 7)) ^ g_t;
            buf[(j >> 4) * RS + (j & 15)] = make_float2(v0[rp], v1[rp]);
        }
        __syncthreads();
        #pragma unroll
        for (int r = 0; r < AMPS; r++) {
            const float2 w2 = buf[baseA + r];    // own row: next write is own row too
            v0[r] = w2.x; v1[r] = w2.y;
        }
    }

    // ---- probabilities ----
    #pragma unroll
    for (int r = 0; r < AMPS; r++) { v0[r] *= v0[r]; v1[r] *= v1[r]; }

    // ---- readout: out[k] = sum_i probs[i] * W[k,i] + b[k], both states ----
    #pragma unroll 1
    for (int k = 0; k < NCLASS; k++) {
        const float4* w4 = reinterpret_cast<const float4*>(W + (size_t)k * DIM)
                         + t * (AMPS / 4);
        float a0 = 0.0f, a1 = 0.0f;
        #pragma unroll
        for (int i = 0; i < AMPS / 4; i++) {
            const float4 w = w4[i];
            a0 = fmaf(v0[4*i+0], w.x, a0);  a1 = fmaf(v1[4*i+0], w.x, a1);
            a0 = fmaf(v0[4*i+1], w.y, a0);  a1 = fmaf(v1[4*i+1], w.y, a1);
            a0 = fmaf(v0[4*i+2], w.z, a0);  a1 = fmaf(v1[4*i+2], w.z, a1);
            a0 = fmaf(v0[4*i+3], w.w, a0);  a1 = fmaf(v1[4*i+3], w.w, a1);
        }
        #pragma unroll
        for (int o = 16; o > 0; o >>= 1) {
            a0 += __shfl_xor_sync(0xffffffffu, a0, o);
            a1 += __shfl_xor_sync(0xffffffffu, a1, o);
        }
        if (lane == 0) sred[k * 8 + warp] = make_float2(a0, a1);
    }
    __syncthreads();
    if (t < NCLASS) {
        float a0 = bias[t], a1 = a0;
        #pragma unroll
        for (int w = 0; w < 8; w++) {
            a0 += sred[t * 8 + w].x;
            a1 += sred[t * 8 + w].y;
        }
        out[(size_t)(2 * bb)     * NCLASS + t] = a0;
        out[(size_t)(2 * bb + 1) * NCLASS + t] = a1;
    }
}

} // namespace

extern "C" void kernel_launch(void* const* d_in, const int* in_sizes, int n_in,
                              void* d_out, int out_size) {
    const float* x      = (const float*)d_in[0];
    const float* angles = (const float*)d_in[1];
    const float* W      = (const float*)d_in[2];
    const float* bias   = (const float*)d_in[3];
    const int batch = in_sizes[0] / FEAT;   // 2048
    qnn_kernel<<<batch / 2, TPB>>>(x, angles, W, bias, (float*)d_out);
}

// round 10
// speedup vs baseline: 2.1487x; 1.0146x over previous
#include <cuda_runtime.h>
#include <cuda_bf16.h>

namespace {

constexpr int NQ     = 12;
constexpr int DIM    = 4096;
constexpr int LAYERS = 8;
constexpr int FEAT   = 3072;
constexpr int NCLASS = 10;
constexpr int TPB    = 256;   // threads per CTA; CTA simulates TWO states
constexpr int AMPS   = 16;    // amplitudes per thread per state
constexpr int RS     = 17;    // smem row stride in u64 units

using u64 = unsigned long long;

// ---- packed f32x2 helpers (sm_100+; SASS FFMA2/FMUL2) ----
__device__ __forceinline__ u64 pack2(float lo, float hi) {
    u64 r; asm("mov.b64 %0, {%1, %2};" : "=l"(r) : "f"(lo), "f"(hi)); return r;
}
__device__ __forceinline__ void unpack2(u64 v, float& lo, float& hi) {
    asm("mov.b64 {%0, %1}, %2;" : "=f"(lo), "=f"(hi) : "l"(v));
}
__device__ __forceinline__ u64 mul2(u64 a, u64 b) {
    u64 r; asm("mul.rn.f32x2 %0, %1, %2;" : "=l"(r) : "l"(a), "l"(b)); return r;
}
__device__ __forceinline__ u64 add2(u64 a, u64 b) {
    u64 r; asm("add.rn.f32x2 %0, %1, %2;" : "=l"(r) : "l"(a), "l"(b)); return r;
}
__device__ __forceinline__ u64 fma2(u64 a, u64 b, u64 c) {
    u64 r; asm("fma.rn.f32x2 %0, %1, %2, %3;" : "=l"(r) : "l"(a), "l"(b), "l"(c)); return r;
}

// Same structure as the 280us scalar kernel, with the two per-CTA states
// fused lane-wise into f32x2 (u64) registers: identical smem layout and
// addresses, identical shfl/LDS counts, but all scalar FFMA pairs become
// single FFMA2 (384 -> 192 math instrs per thread-layer).
//
// Arrangement A: amplitude i = (t<<4) | r   (bits 0-3 register-local)
// Arrangement B: amplitude i = (rp<<8) | t  (bits 8-11 register-local)
// Qubit q acts on bit p = 11 - q. CNOT chain == Gray map j = i ^ (i>>1).
// Tan-form butterflies; cos product folded into normalization.

__global__ void __launch_bounds__(TPB, 3) qnn_kernel(
    const float* __restrict__ x,       // [B, 3072]
    const float* __restrict__ angles,  // [8, 12]
    const float* __restrict__ W,       // [10, 4096]
    const float* __restrict__ bias,    // [10]
    float* __restrict__ out)           // [B, 10]
{
    __shared__ float s_t[LAYERS][NQ];   // tan table [layer][bit pos]
    __shared__ u64   buf[TPB * RS];     // exchange buffer (34816 B)
    __shared__ float s_prod[8];         // per-warp cos products
    __shared__ u64   s_norm[8];         // per-warp sum-of-squares (packed)
    __shared__ u64   sred[8 * NCLASS];  // epilogue partials (packed)

    const int t    = threadIdx.x;
    const int lane = t & 31;
    const int warp = t >> 5;
    const int bb   = blockIdx.x;

    // ---- trig: tan per gate; accumulate global cos product ----
    float cp = 1.0f;
    if (t < LAYERS * NQ) {
        const int l = t / NQ;
        const int q = t - l * NQ;
        const float a = angles[t];
        const int p = NQ - 1 - q;           // qubit q -> bit position p
        const float c = cosf(a);
        s_t[l][p] = sinf(a) / c;
        cp = c;
    }
    #pragma unroll
    for (int o = 16; o > 0; o >>= 1)
        cp *= __shfl_xor_sync(0xffffffffu, cp, o);
    if (lane == 0) s_prod[warp] = cp;

    // ---- load two input rows (pad 3072 -> 4096), packed arrangement A ----
    u64 v[AMPS];
    if (t < FEAT / AMPS) {   // t < 192
        const float4* x0 = reinterpret_cast<const float4*>(x)
                         + (size_t)(2 * bb)     * (FEAT / 4) + t * (AMPS / 4);
        const float4* x1 = reinterpret_cast<const float4*>(x)
                         + (size_t)(2 * bb + 1) * (FEAT / 4) + t * (AMPS / 4);
        #pragma unroll
        for (int i = 0; i < AMPS / 4; i++) {
            const float4 a4 = x0[i];
            const float4 b4 = x1[i];
            v[4*i+0] = pack2(a4.x, b4.x);
            v[4*i+1] = pack2(a4.y, b4.y);
            v[4*i+2] = pack2(a4.z, b4.z);
            v[4*i+3] = pack2(a4.w, b4.w);
        }
    } else {
        #pragma unroll
        for (int r = 0; r < AMPS; r++) v[r] = 0ull;
    }

    // ---- per-state L2 norm (packed), fold in cos product ----
    u64 ssq = 0ull;
    #pragma unroll
    for (int r = 0; r < AMPS; r++) ssq = fma2(v[r], v[r], ssq);
    #pragma unroll
    for (int o = 16; o > 0; o >>= 1)
        ssq = add2(ssq, __shfl_xor_sync(0xffffffffu, ssq, o));
    if (lane == 0) s_norm[warp] = ssq;
    __syncthreads();   // publishes trig table, s_prod, s_norm
    {
        u64 tot = 0ull; float ctot = 1.0f;
        #pragma unroll
        for (int w = 0; w < 8; w++) { tot = add2(tot, s_norm[w]); ctot *= s_prod[w]; }
        float t0, t1; unpack2(tot, t0, t1);
        const u64 rn2 = pack2(rsqrtf(t0) * ctot, rsqrtf(t1) * ctot);
        #pragma unroll
        for (int r = 0; r < AMPS; r++) v[r] = mul2(v[r], rn2);
    }

    const int g_t   = t ^ (t >> 1);                 // 8-bit Gray of thread id
    const int baseA = t * RS;
    const int baseB = (t >> 4) * RS + (t & 15);     // + (rp<<4)*RS per rp

    #pragma unroll 1
    for (int l = 0; l < LAYERS; l++) {
        // ---- gates on bits 0..3 (register butterflies, packed) ----
        #pragma unroll
        for (int p = 0; p < 4; p++) {
            const float tg = s_t[l][p];
            const u64 tg2 = pack2(tg, tg), ntg2 = pack2(-tg, -tg);
            const int m = 1 << p;
            #pragma unroll
            for (int lo = 0; lo < AMPS; lo += 2 * m)
                #pragma unroll
                for (int k = 0; k < m; k++) {
                    const int r0 = lo + k, r1 = r0 + m;
                    const u64 a0 = v[r0], a1 = v[r1];
                    v[r0] = fma2(ntg2, a1, a0);
                    v[r1] = fma2(tg2,  a0, a1);
                }
        }

        // ---- gates on bits 4..7 via shfl_xor (lane bits 0..3) ----
        #pragma unroll
        for (int p = 4; p < 8; p++) {
            const float tg = s_t[l][p];
            const int mask = 1 << (p - 4);
            const float se = (lane & mask) ? tg : -tg;
            const u64 se2 = pack2(se, se);
            #pragma unroll
            for (int r = 0; r < AMPS; r++) {
                const u64 pr = __shfl_xor_sync(0xffffffffu, v[r], mask);
                v[r] = fma2(se2, pr, v[r]);
            }
        }

        // ---- transpose A -> B ----
        #pragma unroll
        for (int r = 0; r < AMPS; r++) buf[baseA + r] = v[r];
        __syncthreads();
        #pragma unroll
        for (int rp = 0; rp < AMPS; rp++) v[rp] = buf[baseB + (rp << 4) * RS];

        // ---- gates on bits 8..11 (register butterflies in B, packed) ----
        #pragma unroll
        for (int p = 0; p < 4; p++) {
            const float tg = s_t[l][p + 8];
            const u64 tg2 = pack2(tg, tg), ntg2 = pack2(-tg, -tg);
            const int m = 1 << p;
            #pragma unroll
            for (int lo = 0; lo < AMPS; lo += 2 * m)
                #pragma unroll
                for (int k = 0; k < m; k++) {
                    const int r0 = lo + k, r1 = r0 + m;
                    const u64 a0 = v[r0], a1 = v[r1];
                    v[r0] = fma2(ntg2, a1, a0);
                    v[r1] = fma2(tg2,  a0, a1);
                }
        }

        __syncthreads();   // WAR: transpose reads complete before scatter

        // ---- Gray scatter B -> A: j = i ^ (i>>1), i = (rp<<8)|t ----
        #pragma unroll
        for (int rp = 0; rp < AMPS; rp++) {
            const int j = ((rp << 8) ^ (rp << 7)) ^ g_t;
            buf[(j >> 4) * RS + (j & 15)] = v[rp];
        }
        __syncthreads();
        #pragma unroll
        for (int r = 0; r < AMPS; r++)
            v[r] = buf[baseA + r];   // own row: next write is own row too

    }

    // ---- probabilities (packed square) ----
    #pragma unroll
    for (int r = 0; r < AMPS; r++) v[r] = mul2(v[r], v[r]);

    // ---- readout: out[k] = sum_i probs[i] * W[k,i] + b[k], both states ----
    #pragma unroll 1
    for (int k = 0; k < NCLASS; k++) {
        const float4* w4 = reinterpret_cast<const float4*>(W + (size_t)k * DIM)
                         + t * (AMPS / 4);
        u64 acc = 0ull;
        #pragma unroll
        for (int i = 0; i < AMPS / 4; i++) {
            const float4 w = w4[i];
            acc = fma2(v[4*i+0], pack2(w.x, w.x), acc);
            acc = fma2(v[4*i+1], pack2(w.y, w.y), acc);
            acc = fma2(v[4*i+2], pack2(w.z, w.z), acc);
            acc = fma2(v[4*i+3], pack2(w.w, w.w), acc);
        }
        #pragma unroll
        for (int o = 16; o > 0; o >>= 1)
            acc = add2(acc, __shfl_xor_sync(0xffffffffu, acc, o));
        if (lane == 0) sred[k * 8 + warp] = acc;
    }
    __syncthreads();
    if (t < NCLASS) {
        u64 tot = 0ull;
        #pragma unroll
        for (int w = 0; w < 8; w++) tot = add2(tot, sred[t * 8 + w]);
        float a0, a1; unpack2(tot, a0, a1);
        const float bk = bias[t];
        out[(size_t)(2 * bb)     * NCLASS + t] = a0 + bk;
        out[(size_t)(2 * bb + 1) * NCLASS + t] = a1 + bk;
    }
}

} // namespace

extern "C" void kernel_launch(void* const* d_in, const int* in_sizes, int n_in,
                              void* d_out, int out_size) {
    const float* x      = (const float*)d_in[0];
    const float* angles = (const float*)d_in[1];
    const float* W      = (const float*)d_in[2];
    const float* bias   = (const float*)d_in[3];
    const int batch = in_sizes[0] / FEAT;   // 2048
    qnn_kernel<<<batch / 2, TPB>>>(x, angles, W, bias, (float*)d_out);
}